// round 1
// baseline (speedup 1.0000x reference)
#include <cuda_runtime.h>
#include <cuda_bf16.h>
#include <math.h>

#define N_NODES 4096
#define N_EDGES 8192
#define D       64
#define D3      67      // D + 3
#define F1      134     // 2*(D+3)  edge-net input
#define F2      201     // 3*(D+3)  node-net input

// ---------------- scratch (device globals; no allocation allowed) -----------
__device__ int   g_seg_i[N_EDGES];
__device__ int   g_seg_o[N_EDGES];
__device__ float g_H0[N_NODES * D3];
__device__ float g_H1[N_NODES * D3];
__device__ float g_EW[N_EDGES];
__device__ float g_MI[N_NODES * D3];
__device__ float g_MO[N_NODES * D3];

// ---------------- 1. recover seg_i / seg_o from one-hot incidence ----------
// Ri, Ro are [N_NODES, N_EDGES] row-major. Ri[n*E + e] == 1 iff seg_i[e] == n.
// Pure bandwidth scan: 268 MB total, float4 loads, coalesced.
__global__ void extract_kernel(const float* __restrict__ Ri,
                               const float* __restrict__ Ro) {
    const unsigned total4 = (unsigned)N_NODES * N_EDGES / 4; // 8,388,608
    unsigned i = blockIdx.x * blockDim.x + threadIdx.x;
    const float4* src;
    int* dst;
    if (i < total4) {
        src = (const float4*)Ri;
        dst = g_seg_i;
    } else {
        i -= total4;
        src = (const float4*)Ro;
        dst = g_seg_o;
    }
    float4 v = src[i];
    unsigned base = i * 4u;
    int n = base >> 13;          // / N_EDGES
    int e = base & (N_EDGES - 1);
    if (v.x != 0.f) dst[e + 0] = n;
    if (v.y != 0.f) dst[e + 1] = n;
    if (v.z != 0.f) dst[e + 2] = n;
    if (v.w != 0.f) dst[e + 3] = n;
}

// ---------------- 2. input net: H = [tanh(X@W_in + b_in), X] ----------------
__global__ void input_kernel(const float* __restrict__ X,
                             const float* __restrict__ W_in,
                             const float* __restrict__ b_in,
                             float* __restrict__ H) {
    int t = blockIdx.x * blockDim.x + threadIdx.x;
    int n = t >> 6;
    int d = t & 63;
    if (n >= N_NODES) return;
    float x0 = X[n * 3 + 0], x1 = X[n * 3 + 1], x2 = X[n * 3 + 2];
    float h = tanhf(x0 * W_in[d] + x1 * W_in[64 + d] + x2 * W_in[128 + d] + b_in[d]);
    H[n * D3 + d] = h;
    if (d < 3) H[n * D3 + D + d] = X[n * 3 + d];
}

// ---------------- 3. edge net -----------------------------------------------
// B = [H[seg_o[e]], H[seg_i[e]]] (134), h = tanh(B@We1+be1) (64),
// out[e] = sigmoid(h@We2 + be2).
// 16 edges per 1024-thread block; We1 staged in shared.
#define EPB 16
__global__ void __launch_bounds__(1024, 1)
edge_kernel(const float* __restrict__ H,
            const float* __restrict__ We1, const float* __restrict__ be1,
            const float* __restrict__ We2, const float* __restrict__ be2,
            float* __restrict__ out) {
    __shared__ float sW[F1 * D];        // 34304 B
    __shared__ float sB[EPB][F1 + 2];   // +2 pad
    __shared__ float sWe2[D];
    __shared__ float sbe1[D];
    __shared__ float sred[EPB * 2];

    int t = threadIdx.x;
    for (int i = t; i < F1 * D; i += 1024) sW[i] = We1[i];
    if (t < D) { sWe2[t] = We2[t]; sbe1[t] = be1[t]; }

    int g = t >> 6;          // edge slot 0..15
    int d = t & 63;
    int e = blockIdx.x * EPB + g;
    int si = g_seg_i[e];
    int so = g_seg_o[e];
    for (int k = d; k < D3; k += 64) {
        sB[g][k]       = H[so * D3 + k];   // bo first
        sB[g][D3 + k]  = H[si * D3 + k];   // then bi
    }
    __syncthreads();

    float acc = sbe1[d];
    const float* B = sB[g];
    #pragma unroll 8
    for (int k = 0; k < F1; k++) acc += B[k] * sW[k * D + d];
    float h = tanhf(acc);
    float p = h * sWe2[d];
    #pragma unroll
    for (int off = 16; off; off >>= 1) p += __shfl_down_sync(0xffffffffu, p, off);
    if ((d & 31) == 0) sred[g * 2 + (d >> 5)] = p;
    __syncthreads();
    if (d == 0) {
        float s = sred[g * 2] + sred[g * 2 + 1] + be2[0];
        out[e] = 1.f / (1.f + __expf(-s));
    }
}

// ---------------- 4. zero message accumulators ------------------------------
__global__ void zero_kernel() {
    int t = blockIdx.x * blockDim.x + threadIdx.x;
    if (t < N_NODES * D3) { g_MI[t] = 0.f; g_MO[t] = 0.f; }
}

// ---------------- 5. weighted scatter ---------------------------------------
// mi[n] += ew[e] * H[seg_o[e]] for e with seg_i[e]==n ; mo symmetric.
__global__ void scatter_kernel(const float* __restrict__ H) {
    int t = blockIdx.x * blockDim.x + threadIdx.x;
    if (t >= N_EDGES * D3) return;
    int e = t / D3;
    int k = t - e * D3;
    float ew = g_EW[e];
    int si = g_seg_i[e];
    int so = g_seg_o[e];
    float bo = H[so * D3 + k];
    float bi = H[si * D3 + k];
    atomicAdd(&g_MI[si * D3 + k], ew * bo);
    atomicAdd(&g_MO[so * D3 + k], ew * bi);
}

// ---------------- 6. node net ------------------------------------------------
// M = [mi, mo, H] (201), h = tanh(M@Wn1+bn1), Hout = [sigmoid(h@Wn2+bn2), X]
#define NPB 8
// dynamic smem layout (floats):
//   Wn1: 201*64 = 12864 | Wn2: 4096 | M: NPB*208 | h: NPB*64 | bn1:64 | bn2:64
#define S_W1 0
#define S_W2 12864
#define S_M  16960
#define S_H  (16960 + NPB * 208)
#define S_B1 (S_H + NPB * 64)
#define S_B2 (S_B1 + 64)
#define NODE_SMEM_FLOATS (S_B2 + 64)

__global__ void __launch_bounds__(512, 1)
node_kernel(const float* __restrict__ Hin, const float* __restrict__ X,
            const float* __restrict__ Wn1, const float* __restrict__ bn1,
            const float* __restrict__ Wn2, const float* __restrict__ bn2,
            float* __restrict__ Hout) {
    extern __shared__ float sm[];
    int t = threadIdx.x;
    for (int i = t; i < F2 * D; i += 512) sm[S_W1 + i] = Wn1[i];
    for (int i = t; i < D * D; i += 512)  sm[S_W2 + i] = Wn2[i];
    if (t < D) { sm[S_B1 + t] = bn1[t]; sm[S_B2 + t] = bn2[t]; }

    int g = t >> 6;
    int d = t & 63;
    int n = blockIdx.x * NPB + g;
    float* M = sm + S_M + g * 208;
    for (int k = d; k < D3; k += 64) {
        M[k]          = g_MI[n * D3 + k];
        M[D3 + k]     = g_MO[n * D3 + k];
        M[2 * D3 + k] = Hin[n * D3 + k];
    }
    __syncthreads();

    float acc = sm[S_B1 + d];
    #pragma unroll 8
    for (int k = 0; k < F2; k++) acc += M[k] * sm[S_W1 + k * D + d];
    sm[S_H + g * 64 + d] = tanhf(acc);
    __syncthreads();

    float acc2 = sm[S_B2 + d];
    const float* hh = sm + S_H + g * 64;
    #pragma unroll 8
    for (int j = 0; j < D; j++) acc2 += hh[j] * sm[S_W2 + j * D + d];
    Hout[n * D3 + d] = 1.f / (1.f + __expf(-acc2));
    if (d < 3) Hout[n * D3 + D + d] = X[n * 3 + d];
}

// ---------------- launcher ---------------------------------------------------
extern "C" void kernel_launch(void* const* d_in, const int* in_sizes, int n_in,
                              void* d_out, int out_size) {
    const float* X    = (const float*)d_in[0];
    const float* Ri   = (const float*)d_in[1];
    const float* Ro   = (const float*)d_in[2];
    const float* W_in = (const float*)d_in[3];
    const float* b_in = (const float*)d_in[4];
    const float* We1  = (const float*)d_in[5];
    const float* be1  = (const float*)d_in[6];
    const float* We2  = (const float*)d_in[7];
    const float* be2  = (const float*)d_in[8];
    const float* Wn1  = (const float*)d_in[9];
    const float* bn1  = (const float*)d_in[10];
    const float* Wn2  = (const float*)d_in[11];
    const float* bn2  = (const float*)d_in[12];
    float* out = (float*)d_out;

    float *pH0, *pH1, *pEW;
    cudaGetSymbolAddress((void**)&pH0, g_H0);
    cudaGetSymbolAddress((void**)&pH1, g_H1);
    cudaGetSymbolAddress((void**)&pEW, g_EW);

    cudaFuncSetAttribute(node_kernel, cudaFuncAttributeMaxDynamicSharedMemorySize,
                         NODE_SMEM_FLOATS * 4);

    // 1. recover edge indices (268 MB scan)
    {
        unsigned total = 2u * (unsigned)N_NODES * N_EDGES / 4;
        extract_kernel<<<total / 256, 256>>>(Ri, Ro);
    }
    // 2. input net
    input_kernel<<<(N_NODES * 64) / 256, 256>>>(X, W_in, b_in, pH0);

    float* Hcur = pH0;
    float* Hnxt = pH1;
    for (int it = 0; it < 3; it++) {
        edge_kernel<<<N_EDGES / EPB, 1024>>>(Hcur, We1, be1, We2, be2, pEW);
        zero_kernel<<<(N_NODES * D3 + 255) / 256, 256>>>();
        scatter_kernel<<<(N_EDGES * D3 + 255) / 256, 256>>>(Hcur);
        node_kernel<<<N_NODES / NPB, 512, NODE_SMEM_FLOATS * 4>>>(
            Hcur, X, Wn1, bn1, Wn2, bn2, Hnxt);
        float* tmp = Hcur; Hcur = Hnxt; Hnxt = tmp;
    }
    // final edge net -> output [E,1]
    edge_kernel<<<N_EDGES / EPB, 1024>>>(Hcur, We1, be1, We2, be2, out);
}

// round 2
// speedup vs baseline: 1.1084x; 1.1084x over previous
#include <cuda_runtime.h>
#include <cuda_bf16.h>
#include <math.h>

#define N_NODES 4096
#define N_EDGES 8192
#define D       64
#define D3      67      // D + 3
#define F1      134     // 2*(D+3)  edge-net input
#define F2      201     // 3*(D+3)  node-net input

// ---------------- scratch (device globals; no allocation allowed) -----------
__device__ int   g_seg_i[N_EDGES];
__device__ int   g_seg_o[N_EDGES];
__device__ __align__(16) float g_H0[N_NODES * D3];
__device__ __align__(16) float g_H1[N_NODES * D3];
__device__ __align__(16) float g_MI[N_NODES * D3];
__device__ __align__(16) float g_MO[N_NODES * D3];
__device__ float g_EW[N_EDGES];   // sink for intermediate edge outputs

// ---------------- 1. recover seg_i / seg_o from one-hot incidence ----------
// Ri, Ro are [N_NODES, N_EDGES] row-major. 268 MB scan, float4, coalesced.
__global__ void extract_kernel(const float* __restrict__ Ri,
                               const float* __restrict__ Ro) {
    const unsigned total4 = (unsigned)N_NODES * N_EDGES / 4; // 8,388,608
    unsigned i = blockIdx.x * blockDim.x + threadIdx.x;
    const float4* src;
    int* dst;
    if (i < total4) {
        src = (const float4*)Ri;
        dst = g_seg_i;
    } else {
        i -= total4;
        src = (const float4*)Ro;
        dst = g_seg_o;
    }
    float4 v = src[i];
    unsigned base = i * 4u;
    int n = base >> 13;          // / N_EDGES
    int e = base & (N_EDGES - 1);
    if (v.x != 0.f) dst[e + 0] = n;
    if (v.y != 0.f) dst[e + 1] = n;
    if (v.z != 0.f) dst[e + 2] = n;
    if (v.w != 0.f) dst[e + 3] = n;
}

// ---------------- 2. input net: H = [tanh(X@W_in + b_in), X] ----------------
__global__ void input_kernel(const float* __restrict__ X,
                             const float* __restrict__ W_in,
                             const float* __restrict__ b_in,
                             float* __restrict__ H) {
    int t = blockIdx.x * blockDim.x + threadIdx.x;
    int n = t >> 6;
    int d = t & 63;
    if (n >= N_NODES) return;
    float x0 = X[n * 3 + 0], x1 = X[n * 3 + 1], x2 = X[n * 3 + 2];
    float h = tanhf(x0 * W_in[d] + x1 * W_in[64 + d] + x2 * W_in[128 + d] + b_in[d]);
    H[n * D3 + d] = h;
    if (d < 3) H[n * D3 + D + d] = X[n * 3 + d];
}

// ---------------- 3. zero message accumulators (float4) ---------------------
__global__ void zero_kernel() {
    const int n4 = N_NODES * D3 / 4;   // 68608
    int t = blockIdx.x * blockDim.x + threadIdx.x;
    float4 z = make_float4(0.f, 0.f, 0.f, 0.f);
    if (t < n4)            ((float4*)g_MI)[t] = z;
    else if (t < 2 * n4)   ((float4*)g_MO)[t - n4] = z;
}

// ---------------- 4. edge net (+ fused weighted scatter) --------------------
// B = [H[so], H[si]] (134), h = tanh(B@We1+be1), ew = sigmoid(h@We2+be2).
// If SCATTER: MI[si] += ew*bo, MO[so] += ew*bi (atomics).
// 32 edges per 256-thread block; thread = 4 output cols (float4 W) x 2 edges.
#define ETPB 32
#define EPAD 136
#define E_W4   0                         // We1 : 134*64 = 8576 floats
#define E_B    8576                      // B   : 32*136 = 4352
#define E_WE2  (E_B + ETPB * EPAD)       // 64
#define E_BE1  (E_WE2 + 64)              // 64
#define E_EW   (E_BE1 + 64)              // 32
#define E_SI   (E_EW + ETPB)             // 32 ints
#define E_SO   (E_SI + ETPB)             // 32 ints
#define E_SMEM_FLOATS (E_SO + ETPB)      // 13152 floats = 52608 B

template<bool SCATTER>
__global__ void __launch_bounds__(256)
edge_kernel(const float* __restrict__ H,
            const float* __restrict__ We1, const float* __restrict__ be1,
            const float* __restrict__ We2, const float* __restrict__ be2,
            float* __restrict__ out) {
    extern __shared__ float sm[];
    int t = threadIdx.x;
    for (int i = t; i < F1 * D; i += 256) sm[E_W4 + i] = We1[i];
    if (t < D) { sm[E_WE2 + t] = We2[t]; sm[E_BE1 + t] = be1[t]; }
    int* sSi = (int*)(sm + E_SI);
    int* sSo = (int*)(sm + E_SO);
    int e0 = blockIdx.x * ETPB;
    if (t < ETPB) { sSi[t] = g_seg_i[e0 + t]; sSo[t] = g_seg_o[e0 + t]; }
    __syncthreads();

    // gather B = [bo | bi] into smem
    for (int i = t; i < ETPB * F1; i += 256) {
        int j = i / F1, k = i - j * F1;
        float v = (k < D3) ? H[sSo[j] * D3 + k] : H[sSi[j] * D3 + (k - D3)];
        sm[E_B + j * EPAD + k] = v;
    }
    __syncthreads();

    int dg = t & 15;            // output cols 4*dg .. 4*dg+3
    int eg = t >> 4;            // edge pair
    int ja = eg * 2, jb = ja + 1;
    const float4* W4 = (const float4*)(sm + E_W4);
    const float* Ba = sm + E_B + ja * EPAD;
    const float* Bb = sm + E_B + jb * EPAD;

    float b0 = sm[E_BE1 + 4 * dg + 0], b1 = sm[E_BE1 + 4 * dg + 1];
    float b2 = sm[E_BE1 + 4 * dg + 2], b3 = sm[E_BE1 + 4 * dg + 3];
    float4 A = make_float4(b0, b1, b2, b3);
    float4 Bv = make_float4(b0, b1, b2, b3);
    #pragma unroll 2
    for (int k = 0; k < F1; k++) {
        float4 w = W4[k * 16 + dg];
        float ba = Ba[k], bb = Bb[k];
        A.x += ba * w.x; A.y += ba * w.y; A.z += ba * w.z; A.w += ba * w.w;
        Bv.x += bb * w.x; Bv.y += bb * w.y; Bv.z += bb * w.z; Bv.w += bb * w.w;
    }
    float w20 = sm[E_WE2 + 4 * dg + 0], w21 = sm[E_WE2 + 4 * dg + 1];
    float w22 = sm[E_WE2 + 4 * dg + 2], w23 = sm[E_WE2 + 4 * dg + 3];
    float pa = tanhf(A.x) * w20 + tanhf(A.y) * w21 + tanhf(A.z) * w22 + tanhf(A.w) * w23;
    float pb = tanhf(Bv.x) * w20 + tanhf(Bv.y) * w21 + tanhf(Bv.z) * w22 + tanhf(Bv.w) * w23;
    #pragma unroll
    for (int off = 8; off; off >>= 1) {
        pa += __shfl_down_sync(0xffffffffu, pa, off, 16);
        pb += __shfl_down_sync(0xffffffffu, pb, off, 16);
    }
    if (dg == 0) {
        float bb2 = be2[0];
        float ea = 1.f / (1.f + __expf(-(pa + bb2)));
        float eb = 1.f / (1.f + __expf(-(pb + bb2)));
        out[e0 + ja] = ea;  out[e0 + jb] = eb;
        sm[E_EW + ja] = ea; sm[E_EW + jb] = eb;
    }
    if (SCATTER) {
        __syncthreads();
        for (int i = t; i < ETPB * D3; i += 256) {
            int j = i / D3, k = i - j * D3;
            float ew = sm[E_EW + j];
            float bo = sm[E_B + j * EPAD + k];
            float bi = sm[E_B + j * EPAD + D3 + k];
            atomicAdd(&g_MI[sSi[j] * D3 + k], ew * bo);
            atomicAdd(&g_MO[sSo[j] * D3 + k], ew * bi);
        }
    }
}

// ---------------- 5. node net -----------------------------------------------
// M = [mi, mo, H] (201), h = tanh(M@Wn1+bn1), Hout = [sigmoid(h@Wn2+bn2), X]
// 16 nodes per 256-thread block; thread = 4 output cols x 1 node.
#define NTPB 16
#define NPAD 202
#define N_W1   0                          // 201*64 = 12864
#define N_W2   12864                      // 64*64  = 4096
#define N_M    16960                      // 16*202 = 3232
#define N_H    (N_M + NTPB * NPAD)        // 16*64  = 1024
#define N_B1   (N_H + NTPB * 64)          // 64
#define N_B2   (N_B1 + 64)                // 64
#define N_SMEM_FLOATS (N_B2 + 64)         // 21344 floats = 85376 B

__global__ void __launch_bounds__(256)
node_kernel(const float* __restrict__ Hin, const float* __restrict__ X,
            const float* __restrict__ Wn1, const float* __restrict__ bn1,
            const float* __restrict__ Wn2, const float* __restrict__ bn2,
            float* __restrict__ Hout) {
    extern __shared__ float sm[];
    int t = threadIdx.x;
    for (int i = t; i < F2 * D; i += 256) sm[N_W1 + i] = Wn1[i];
    for (int i = t; i < D * D; i += 256)  sm[N_W2 + i] = Wn2[i];
    if (t < D) { sm[N_B1 + t] = bn1[t]; sm[N_B2 + t] = bn2[t]; }
    int n0 = blockIdx.x * NTPB;

    // gather M = [mi | mo | H]
    for (int i = t; i < NTPB * F2; i += 256) {
        int j = i / F2, k = i - j * F2;
        int n = n0 + j;
        float v;
        if (k < D3)            v = g_MI[n * D3 + k];
        else if (k < 2 * D3)   v = g_MO[n * D3 + (k - D3)];
        else                   v = Hin[n * D3 + (k - 2 * D3)];
        sm[N_M + j * NPAD + k] = v;
    }
    __syncthreads();

    int dg = t & 15;
    int ng = t >> 4;
    int n = n0 + ng;
    const float4* W14 = (const float4*)(sm + N_W1);
    const float* M = sm + N_M + ng * NPAD;

    float4 A = make_float4(sm[N_B1 + 4 * dg + 0], sm[N_B1 + 4 * dg + 1],
                           sm[N_B1 + 4 * dg + 2], sm[N_B1 + 4 * dg + 3]);
    #pragma unroll 3
    for (int k = 0; k < F2; k++) {
        float4 w = W14[k * 16 + dg];
        float b = M[k];
        A.x += b * w.x; A.y += b * w.y; A.z += b * w.z; A.w += b * w.w;
    }
    float* hh = sm + N_H + ng * 64;
    hh[4 * dg + 0] = tanhf(A.x);
    hh[4 * dg + 1] = tanhf(A.y);
    hh[4 * dg + 2] = tanhf(A.z);
    hh[4 * dg + 3] = tanhf(A.w);
    __syncthreads();

    const float4* W24 = (const float4*)(sm + N_W2);
    float4 A2 = make_float4(sm[N_B2 + 4 * dg + 0], sm[N_B2 + 4 * dg + 1],
                            sm[N_B2 + 4 * dg + 2], sm[N_B2 + 4 * dg + 3]);
    #pragma unroll 4
    for (int j2 = 0; j2 < D; j2++) {
        float4 w = W24[j2 * 16 + dg];
        float h = hh[j2];
        A2.x += h * w.x; A2.y += h * w.y; A2.z += h * w.z; A2.w += h * w.w;
    }
    Hout[n * D3 + 4 * dg + 0] = 1.f / (1.f + __expf(-A2.x));
    Hout[n * D3 + 4 * dg + 1] = 1.f / (1.f + __expf(-A2.y));
    Hout[n * D3 + 4 * dg + 2] = 1.f / (1.f + __expf(-A2.z));
    Hout[n * D3 + 4 * dg + 3] = 1.f / (1.f + __expf(-A2.w));
    if (dg < 3) Hout[n * D3 + D + dg] = X[n * 3 + dg];
}

// ---------------- launcher ---------------------------------------------------
extern "C" void kernel_launch(void* const* d_in, const int* in_sizes, int n_in,
                              void* d_out, int out_size) {
    const float* X    = (const float*)d_in[0];
    const float* Ri   = (const float*)d_in[1];
    const float* Ro   = (const float*)d_in[2];
    const float* W_in = (const float*)d_in[3];
    const float* b_in = (const float*)d_in[4];
    const float* We1  = (const float*)d_in[5];
    const float* be1  = (const float*)d_in[6];
    const float* We2  = (const float*)d_in[7];
    const float* be2  = (const float*)d_in[8];
    const float* Wn1  = (const float*)d_in[9];
    const float* bn1  = (const float*)d_in[10];
    const float* Wn2  = (const float*)d_in[11];
    const float* bn2  = (const float*)d_in[12];
    float* out = (float*)d_out;

    float *pH0, *pH1, *pEW;
    cudaGetSymbolAddress((void**)&pH0, g_H0);
    cudaGetSymbolAddress((void**)&pH1, g_H1);
    cudaGetSymbolAddress((void**)&pEW, g_EW);

    static int attr_done = 0;
    if (!attr_done) {
        cudaFuncSetAttribute(edge_kernel<true>,
                             cudaFuncAttributeMaxDynamicSharedMemorySize,
                             E_SMEM_FLOATS * 4);
        cudaFuncSetAttribute(edge_kernel<false>,
                             cudaFuncAttributeMaxDynamicSharedMemorySize,
                             E_SMEM_FLOATS * 4);
        cudaFuncSetAttribute(node_kernel,
                             cudaFuncAttributeMaxDynamicSharedMemorySize,
                             N_SMEM_FLOATS * 4);
        attr_done = 1;
    }

    // 1. recover edge indices (268 MB scan)
    {
        unsigned total = 2u * (unsigned)N_NODES * N_EDGES / 4;
        extract_kernel<<<total / 256, 256>>>(Ri, Ro);
    }
    // 2. input net
    input_kernel<<<(N_NODES * 64) / 256, 256>>>(X, W_in, b_in, pH0);

    float* Hcur = pH0;
    float* Hnxt = pH1;
    for (int it = 0; it < 3; it++) {
        zero_kernel<<<(2 * (N_NODES * D3 / 4) + 255) / 256, 256>>>();
        edge_kernel<true><<<N_EDGES / ETPB, 256, E_SMEM_FLOATS * 4>>>(
            Hcur, We1, be1, We2, be2, pEW);
        node_kernel<<<N_NODES / NTPB, 256, N_SMEM_FLOATS * 4>>>(
            Hcur, X, Wn1, bn1, Wn2, bn2, Hnxt);
        float* tmp = Hcur; Hcur = Hnxt; Hnxt = tmp;
    }
    // final edge net -> output [E,1]
    edge_kernel<false><<<N_EDGES / ETPB, 256, E_SMEM_FLOATS * 4>>>(
        Hcur, We1, be1, We2, be2, out);
}

// round 3
// speedup vs baseline: 1.3428x; 1.2115x over previous
#include <cuda_runtime.h>
#include <cuda_bf16.h>
#include <math.h>

#define N_NODES 4096
#define N_EDGES 8192
#define D       64
#define D3      67      // D + 3
#define F1      134     // 2*(D+3)
#define F2      201     // 3*(D+3)

// ---------------- device scratch (no allocation allowed) --------------------
__device__ int   g_seg_i[N_EDGES];
__device__ int   g_seg_o[N_EDGES];
__device__ __align__(16) float g_H0[N_NODES * D3];
__device__ __align__(16) float g_H1[N_NODES * D3];
__device__ __align__(16) float g_MI[N_NODES * D3];   // zero-init at load; re-zeroed by node phase
__device__ __align__(16) float g_MO[N_NODES * D3];

// grid barrier state (monotone generation; count reset by releaser)
__device__ unsigned g_bar_count = 0;
__device__ volatile unsigned g_bar_gen = 0;

// ---------------- smem layout (floats) --------------------------------------
#define S_WE1 0                       // 134*64 = 8576
#define S_WN1 8576                    // 201*64 = 12864
#define S_WN2 (8576 + 12864)          // 21440 : 64*64 = 4096
#define S_BE1 (21440 + 4096)          // 25536 : 64
#define S_WE2 (S_BE1 + 64)            // 25600 : 64
#define S_BN1 (S_WE2 + 64)            // 25664 : 64
#define S_BN2 (S_BN1 + 64)            // 25728 : 64
#define S_BUF (S_BN2 + 64)            // 25792 : union buffer (8768 floats)
#define ET    64                      // edges per tile
#define EPAD  137
#define NT    32                      // nodes per tile
#define NPAD  203
#define S_EW  (S_BUF + 8768)          // 34560 : 64
#define S_SI  (S_EW + 64)             // 34624 : 64 ints
#define S_SO  (S_SI + 64)             // 34688 : 64 ints
#define SMEM_FLOATS (S_SO + 64)       // 34752 floats = 139008 B

// ---------------- grid-wide barrier -----------------------------------------
__device__ __forceinline__ void grid_sync(int nblocks) {
    __syncthreads();
    if (threadIdx.x == 0) {
        __threadfence();
        unsigned gen = g_bar_gen;
        if (atomicAdd(&g_bar_count, 1u) == (unsigned)nblocks - 1u) {
            g_bar_count = 0u;
            __threadfence();
            g_bar_gen = gen + 1u;
        } else {
            while (g_bar_gen == gen) { __nanosleep(32); }
        }
        __threadfence();
    }
    __syncthreads();
}

// ---------------- phase 0: extract indices + input net ----------------------
__device__ void extract_input_phase(const float* __restrict__ Ri,
                                    const float* __restrict__ Ro,
                                    const float* __restrict__ X,
                                    const float* __restrict__ W_in,
                                    const float* __restrict__ b_in,
                                    int nblocks) {
    const unsigned total4 = (unsigned)N_NODES * N_EDGES / 4;   // 8,388,608
    unsigned stride = (unsigned)nblocks * 1024u;
    for (unsigned i = blockIdx.x * 1024u + threadIdx.x; i < 2u * total4; i += stride) {
        const float4* src; int* dst; unsigned ii = i;
        if (ii < total4) { src = (const float4*)Ri; dst = g_seg_i; }
        else             { ii -= total4; src = (const float4*)Ro; dst = g_seg_o; }
        float4 v = __ldcs(&src[ii]);
        unsigned base = ii * 4u;
        int n = base >> 13;
        int e = base & (N_EDGES - 1);
        if (v.x != 0.f) dst[e + 0] = n;
        if (v.y != 0.f) dst[e + 1] = n;
        if (v.z != 0.f) dst[e + 2] = n;
        if (v.w != 0.f) dst[e + 3] = n;
    }
    // input net: H0 = [tanh(X@W_in + b_in), X]
    for (int i = blockIdx.x * 1024 + threadIdx.x; i < N_NODES * D; i += nblocks * 1024) {
        int n = i >> 6, d = i & 63;
        float x0 = X[n * 3 + 0], x1 = X[n * 3 + 1], x2 = X[n * 3 + 2];
        float h = tanhf(x0 * W_in[d] + x1 * W_in[64 + d] + x2 * W_in[128 + d] + b_in[d]);
        g_H0[n * D3 + d] = h;
        if (d < 3) g_H0[n * D3 + D + d] = X[n * 3 + d];
    }
}

// ---------------- edge phase (+ optional fused scatter) ---------------------
template<bool SCATTER>
__device__ void edge_phase(const float* __restrict__ H, float* __restrict__ out,
                           const float* __restrict__ be2, float* sm, int nblocks) {
    int t = threadIdx.x;
    for (int tile = blockIdx.x; tile < N_EDGES / ET; tile += nblocks) {
        int e0 = tile * ET;
        int* sSi = (int*)(sm + S_SI);
        int* sSo = (int*)(sm + S_SO);
        if (t < ET) { sSi[t] = g_seg_i[e0 + t]; sSo[t] = g_seg_o[e0 + t]; }
        __syncthreads();
        // gather B = [bo | bi]
        for (int i = t; i < ET * F1; i += 1024) {
            int j = i / F1, k = i - j * F1;
            float v = (k < D3) ? H[sSo[j] * D3 + k] : H[sSi[j] * D3 + (k - D3)];
            sm[S_BUF + j * EPAD + k] = v;
        }
        __syncthreads();
        if (t < 512) {
            int dg = t & 15;          // 4 output cols
            int ep = t >> 4;          // edge pair 0..31
            int ja = 2 * ep, jb = ja + 1;
            const float4* W4 = (const float4*)(sm + S_WE1);
            const float* Ba = sm + S_BUF + ja * EPAD;
            const float* Bb = sm + S_BUF + jb * EPAD;
            float4 bias = ((const float4*)(sm + S_BE1))[dg];
            float4 A = bias, Bv = bias;
            #pragma unroll 2
            for (int k = 0; k < F1; k++) {
                float4 w = W4[k * 16 + dg];
                float ba = Ba[k], bb = Bb[k];
                A.x += ba * w.x; A.y += ba * w.y; A.z += ba * w.z; A.w += ba * w.w;
                Bv.x += bb * w.x; Bv.y += bb * w.y; Bv.z += bb * w.z; Bv.w += bb * w.w;
            }
            float4 w2 = ((const float4*)(sm + S_WE2))[dg];
            float pa = tanhf(A.x) * w2.x + tanhf(A.y) * w2.y + tanhf(A.z) * w2.z + tanhf(A.w) * w2.w;
            float pb = tanhf(Bv.x) * w2.x + tanhf(Bv.y) * w2.y + tanhf(Bv.z) * w2.z + tanhf(Bv.w) * w2.w;
            #pragma unroll
            for (int off = 8; off; off >>= 1) {
                pa += __shfl_down_sync(0xffffffffu, pa, off, 16);
                pb += __shfl_down_sync(0xffffffffu, pb, off, 16);
            }
            if (dg == 0) {
                float bb2 = be2[0];
                float ea = 1.f / (1.f + __expf(-(pa + bb2)));
                float eb = 1.f / (1.f + __expf(-(pb + bb2)));
                sm[S_EW + ja] = ea; sm[S_EW + jb] = eb;
                if (!SCATTER) { out[e0 + ja] = ea; out[e0 + jb] = eb; }
            }
        }
        __syncthreads();
        if (SCATTER) {
            for (int i = t; i < ET * D3; i += 1024) {
                int j = i / D3, k = i - j * D3;
                float ew = sm[S_EW + j];
                atomicAdd(&g_MI[sSi[j] * D3 + k], ew * sm[S_BUF + j * EPAD + k]);
                atomicAdd(&g_MO[sSo[j] * D3 + k], ew * sm[S_BUF + j * EPAD + D3 + k]);
            }
            __syncthreads();
        }
    }
}

// ---------------- node phase (+ fused re-zero of MI/MO) ---------------------
__device__ void node_phase(const float* __restrict__ Hin, float* __restrict__ Hout,
                           const float* __restrict__ X, float* sm, int nblocks) {
    int t = threadIdx.x;
    for (int tile = blockIdx.x; tile < N_NODES / NT; tile += nblocks) {
        int n0 = tile * NT;
        // gather M = [mi | mo | H]
        for (int i = t; i < NT * F2; i += 1024) {
            int j = i / F2, k = i - j * F2;
            int n = n0 + j;
            float v;
            if (k < D3)          v = g_MI[n * D3 + k];
            else if (k < 2 * D3) v = g_MO[n * D3 + (k - D3)];
            else                 v = Hin[n * D3 + (k - 2 * D3)];
            sm[S_BUF + j * NPAD + k] = v;
        }
        __syncthreads();
        float* hbuf = sm + S_BUF + NT * NPAD;   // 32*64 floats
        if (t < 256) {
            int dg = t & 15;
            int np = t >> 4;              // 0..15 -> node pair
            int ja = 2 * np, jb = ja + 1;
            const float4* W4 = (const float4*)(sm + S_WN1);
            const float* Ma = sm + S_BUF + ja * NPAD;
            const float* Mb = sm + S_BUF + jb * NPAD;
            float4 bias = ((const float4*)(sm + S_BN1))[dg];
            float4 A = bias, Bv = bias;
            #pragma unroll 3
            for (int k = 0; k < F2; k++) {
                float4 w = W4[k * 16 + dg];
                float ma = Ma[k], mb = Mb[k];
                A.x += ma * w.x; A.y += ma * w.y; A.z += ma * w.z; A.w += ma * w.w;
                Bv.x += mb * w.x; Bv.y += mb * w.y; Bv.z += mb * w.z; Bv.w += mb * w.w;
            }
            hbuf[ja * 64 + 4 * dg + 0] = tanhf(A.x);
            hbuf[ja * 64 + 4 * dg + 1] = tanhf(A.y);
            hbuf[ja * 64 + 4 * dg + 2] = tanhf(A.z);
            hbuf[ja * 64 + 4 * dg + 3] = tanhf(A.w);
            hbuf[jb * 64 + 4 * dg + 0] = tanhf(Bv.x);
            hbuf[jb * 64 + 4 * dg + 1] = tanhf(Bv.y);
            hbuf[jb * 64 + 4 * dg + 2] = tanhf(Bv.z);
            hbuf[jb * 64 + 4 * dg + 3] = tanhf(Bv.w);
        }
        __syncthreads();
        if (t < 256) {
            int dg = t & 15;
            int np = t >> 4;
            int ja = 2 * np, jb = ja + 1;
            const float4* W24 = (const float4*)(sm + S_WN2);
            float4 bias2 = ((const float4*)(sm + S_BN2))[dg];
            float4 A2 = bias2, B2 = bias2;
            const float* ha = hbuf + ja * 64;
            const float* hb = hbuf + jb * 64;
            #pragma unroll 4
            for (int j2 = 0; j2 < D; j2++) {
                float4 w = W24[j2 * 16 + dg];
                float va = ha[j2], vb = hb[j2];
                A2.x += va * w.x; A2.y += va * w.y; A2.z += va * w.z; A2.w += va * w.w;
                B2.x += vb * w.x; B2.y += vb * w.y; B2.z += vb * w.z; B2.w += vb * w.w;
            }
            float* oa = Hout + (n0 + ja) * D3 + 4 * dg;
            float* ob = Hout + (n0 + jb) * D3 + 4 * dg;
            oa[0] = 1.f / (1.f + __expf(-A2.x));
            oa[1] = 1.f / (1.f + __expf(-A2.y));
            oa[2] = 1.f / (1.f + __expf(-A2.z));
            oa[3] = 1.f / (1.f + __expf(-A2.w));
            ob[0] = 1.f / (1.f + __expf(-B2.x));
            ob[1] = 1.f / (1.f + __expf(-B2.y));
            ob[2] = 1.f / (1.f + __expf(-B2.z));
            ob[3] = 1.f / (1.f + __expf(-B2.w));
        }
        // re-zero MI/MO for this tile (next iteration / next launch)
        for (int i = t; i < NT * D3; i += 1024) {
            int j = i / D3, k = i - j * D3;
            g_MI[(n0 + j) * D3 + k] = 0.f;
            g_MO[(n0 + j) * D3 + k] = 0.f;
        }
        if (t < NT * 3) {
            int j = t / 3, c = t - j * 3;
            Hout[(n0 + j) * D3 + D + c] = X[(n0 + j) * 3 + c];
        }
        __syncthreads();
    }
}

// ---------------- persistent kernel ------------------------------------------
__global__ void __launch_bounds__(1024, 1)
gnn_persistent(const float* __restrict__ X,
               const float* __restrict__ Ri,  const float* __restrict__ Ro,
               const float* __restrict__ W_in, const float* __restrict__ b_in,
               const float* __restrict__ We1, const float* __restrict__ be1,
               const float* __restrict__ We2, const float* __restrict__ be2,
               const float* __restrict__ Wn1, const float* __restrict__ bn1,
               const float* __restrict__ Wn2, const float* __restrict__ bn2,
               float* __restrict__ out, int nblocks) {
    extern __shared__ float sm[];
    int t = threadIdx.x;
    // stage all weights once per block
    for (int i = t; i < F1 * D; i += 1024) sm[S_WE1 + i] = We1[i];
    for (int i = t; i < F2 * D; i += 1024) sm[S_WN1 + i] = Wn1[i];
    for (int i = t; i < D * D;  i += 1024) sm[S_WN2 + i] = Wn2[i];
    if (t < 64) {
        sm[S_BE1 + t] = be1[t];
        sm[S_WE2 + t] = We2[t];
        sm[S_BN1 + t] = bn1[t];
        sm[S_BN2 + t] = bn2[t];
    }

    extract_input_phase(Ri, Ro, X, W_in, b_in, nblocks);
    grid_sync(nblocks);

    float* Hc = g_H0;
    float* Hn = g_H1;
    #pragma unroll 1
    for (int it = 0; it < 3; it++) {
        edge_phase<true>(Hc, nullptr, be2, sm, nblocks);
        grid_sync(nblocks);
        node_phase(Hc, Hn, X, sm, nblocks);
        grid_sync(nblocks);
        float* tmp = Hc; Hc = Hn; Hn = tmp;
    }
    edge_phase<false>(Hc, out, be2, sm, nblocks);
}

// ---------------- launcher ----------------------------------------------------
extern "C" void kernel_launch(void* const* d_in, const int* in_sizes, int n_in,
                              void* d_out, int out_size) {
    const float* X    = (const float*)d_in[0];
    const float* Ri   = (const float*)d_in[1];
    const float* Ro   = (const float*)d_in[2];
    const float* W_in = (const float*)d_in[3];
    const float* b_in = (const float*)d_in[4];
    const float* We1  = (const float*)d_in[5];
    const float* be1  = (const float*)d_in[6];
    const float* We2  = (const float*)d_in[7];
    const float* be2  = (const float*)d_in[8];
    const float* Wn1  = (const float*)d_in[9];
    const float* bn1  = (const float*)d_in[10];
    const float* Wn2  = (const float*)d_in[11];
    const float* bn2  = (const float*)d_in[12];
    float* out = (float*)d_out;

    int dev = 0, nsm = 0;
    cudaGetDevice(&dev);
    cudaDeviceGetAttribute(&nsm, cudaDevAttrMultiProcessorCount, dev);

    cudaFuncSetAttribute(gnn_persistent, cudaFuncAttributeMaxDynamicSharedMemorySize,
                         SMEM_FLOATS * 4);

    gnn_persistent<<<nsm, 1024, SMEM_FLOATS * 4>>>(
        X, Ri, Ro, W_in, b_in, We1, be1, We2, be2, Wn1, bn1, Wn2, bn2, out, nsm);
}